// round 5
// baseline (speedup 1.0000x reference)
#include <cuda_runtime.h>
#include <math.h>
#include <stdint.h>

#define BATCH 16
#define KBOX  128
#define NUMC  80
#define OH    128
#define OW    128
#define NB    (BATCH*KBOX)
#define PLANE (OH*OW)
#define TOT4  (BATCH*NUMC*PLANE/4)     // 5,242,880 float4
#define NSTREAM 2560                   // TOT4 / (256*8)
#define NPREP   16
#define NBLK    (NPREP + NSTREAM)      // 2576
#define NSPARSE 1024                   // 2 rows each -> 2048 rows

// ---- per-box scratch (sorted order) ----
__device__ float d_bx1[NB], d_by1[NB], d_bx2[NB], d_by2[NB];
__device__ float d_i2sy[NB], d_i2sx[NB], d_coef[NB];
__device__ int   d_cls[NB], d_cx[NB], d_cy[NB], d_hr[NB], d_wr[NB], d_act[NB];

// ---- per-block partials + sync counters ----
__device__ float d_part_hm[NBLK], d_part_whn[NBLK], d_part_rw[NBLK];
__device__ int   d_part_np[NBLK];
__device__ int   d_prep_ctr;     // self-resetting
__device__ unsigned int d_done_ctr;

// u(x) = log(1 - clip(sigmoid(x))) * clip(sigmoid(x))^2
__device__ __forceinline__ float focal_neg_base(float xv, float& p_out) {
    float t = __expf(-xv);
    float p = __fdividef(1.0f, 1.0f + t);
    p = fminf(fmaxf(p, 1e-4f), 0.9999f);
    p_out = p;
    float omp = 1.0f - p;
    return __logf(omp) * p * p;
}

__global__ void __launch_bounds__(256, 4)
mega_kernel(const float* __restrict__ hm,
            const float* __restrict__ wh,
            const float* __restrict__ tgt,
            const void*  __restrict__ mraw,
            float* __restrict__ out) {
    int bid = blockIdx.x;
    int tid = threadIdx.x;
    int lane = tid & 31;
    int wrp  = tid >> 5;

    float lsum = 0.0f, lwhn = 0.0f, lrw = 0.0f;
    int   lnp  = 0;

    // ------------- shared (union by co-existence is fine; total ~10KB) ----
    __shared__ float skey[KBOX];
    __shared__ int   sperm[KBOX];
    __shared__ int   smask[KBOX];
    __shared__ float s_al0;
    __shared__ int   s_gt1, s_off4;

    __shared__ float sx1[KBOX], sy1s[KBOX], sx2[KBOX], sy2s[KBOX];
    __shared__ float scoef[KBOX], si2sx[KBOX];
    __shared__ int   scx[KBOX], swr[KBOX], scls[KBOX];
    __shared__ float sgy2[2][KBOX];
    __shared__ short slist2[2][KBOX];
    __shared__ int   s_n2[2];

    if (bid < NPREP) {
        // ================= PREP for image b = bid =================
        int b = bid;
        int k = tid;  // only k<128 does per-box work
        if (tid == 0) { s_gt1 = 0; s_off4 = 0; }
        __syncthreads();
        {
            const uint8_t* b8 = (const uint8_t*)mraw;
            int gt1 = 0, off4 = 0;
            for (int i = tid; i < NB; i += 256) {
                uint8_t v = b8[i];
                gt1  |= (v > 1);
                off4 |= (v != 0) && ((i & 3) != 0);
            }
            if (gt1)  atomicOr(&s_gt1, 1);
            if (off4) atomicOr(&s_off4, 1);
        }
        __syncthreads();
        int u8mode = (!s_gt1) && s_off4;
        if (k < KBOX) {
            int i = b*KBOX + k;
            smask[k] = u8mode ? (((const uint8_t*)mraw)[i] != 0)
                              : (((const uint32_t*)mraw)[i] != 0u);
        }
        __syncthreads();
        if (k < KBOX) {
            const float* t = tgt + (size_t)(b*KBOX + k)*5;
            float x1 = t[1], y1 = t[2], x2 = t[3], y2 = t[4];
            float area = (x2 - x1) * (y2 - y1);
            skey[k] = smask[k] ? __logf(area) : -INFINITY;
        }
        __syncthreads();
        if (k < KBOX) {
            float key = skey[k];
            int rank = 0;
#pragma unroll 16
            for (int j = 0; j < KBOX; j++) {
                float kj = skey[j];
                rank += (kj > key) || (kj == key && j < k);
            }
            sperm[rank] = k;
        }
        __syncthreads();
        if (tid == 0) {
            int o0 = sperm[0];
            s_al0 = smask[o0] ? skey[o0] : 0.0f;
        }
        __syncthreads();
        if (k < KBOX) {
            int o = sperm[k];
            const float* to = tgt + (size_t)(b*KBOX + o)*5;
            float clsf = to[0];
            float ox1 = to[1], oy1 = to[2], ox2 = to[3], oy2 = to[4];
            int v = smask[o];
            float keyo = skey[o];

            float fx1 = fminf(fmaxf(ox1 * 0.25f, 0.0f), (float)(OW-1));
            float fy1 = fminf(fmaxf(oy1 * 0.25f, 0.0f), (float)(OH-1));
            float fx2 = fminf(fmaxf(ox2 * 0.25f, 0.0f), (float)(OW-1));
            float fy2 = fminf(fmaxf(oy2 * 0.25f, 0.0f), (float)(OH-1));
            float feat_h = fy2 - fy1;
            float feat_w = fx2 - fx1;

            int cx = (int)(((ox1 + ox2) * 0.5f) * 0.25f);
            int cy = (int)(((oy1 + oy2) * 0.5f) * 0.25f);
            int hr = (int)((feat_h * 0.5f) * 0.54f);
            int wr = (int)((feat_w * 0.5f) * 0.54f);
            float sy = (float)(2*hr + 1) / 6.0f;
            float sx = (float)(2*wr + 1) / 6.0f;
            float i2sy = 1.0f / (2.0f * sy * sy);
            float i2sx = 1.0f / (2.0f * sx * sx);

            int act = v && (cx >= 0) && (cx < OW) && (cy >= 0) && (cy < OH);

            float divs = 0.0f;
            if (act) {
                float sgy = 0.0f, sgx = 0.0f;
                int ya = max(0, cy - hr), yb = min(OH-1, cy + hr);
                for (int yy = ya; yy <= yb; yy++) {
                    float d = (float)(yy - cy);
                    sgy += __expf(-(d*d) * i2sy);
                }
                int xa = max(0, cx - wr), xb = min(OW-1, cx + wr);
                for (int xx = xa; xx <= xb; xx++) {
                    float d = (float)(xx - cx);
                    sgx += __expf(-(d*d) * i2sx);
                }
                divs = sgy * sgx;
            }
            float al = v ? keyo : 0.0f;
            float factor = 2.0f - al / (s_al0 + 1e-7f);
            float coef = act ? (factor / (divs + 1e-7f)) : 0.0f;

            int idx = b*KBOX + k;
            d_bx1[idx] = ox1; d_by1[idx] = oy1; d_bx2[idx] = ox2; d_by2[idx] = oy2;
            d_i2sy[idx] = i2sy; d_i2sx[idx] = i2sx; d_coef[idx] = coef;
            d_cls[idx] = (int)clsf; d_cx[idx] = cx; d_cy[idx] = cy;
            d_hr[idx] = hr; d_wr[idx] = wr; d_act[idx] = act;
        }
        __threadfence();
        __syncthreads();
        if (tid == 0) atomicAdd(&d_prep_ctr, 1);
    } else {
        // ================= STREAM base focal term =================
        int sid = bid - NPREP;
        const float4* hm4 = (const float4*)hm;
        int idx = sid * 2048 + tid;
        float4 v[8];
#pragma unroll
        for (int u = 0; u < 8; u++) v[u] = __ldg(&hm4[idx + u*256]);
#pragma unroll
        for (int u = 0; u < 8; u++) {
            float p;
            lsum += focal_neg_base(v[u].x, p);
            lsum += focal_neg_base(v[u].y, p);
            lsum += focal_neg_base(v[u].z, p);
            lsum += focal_neg_base(v[u].w, p);
        }

        if (sid < NSPARSE) {
            // ================= SPARSE: 2 rows of image b =================
            int b = sid >> 6;
            int y0 = (sid & 63) * 2;
            int half = tid >> 7;          // 0 or 1
            int x = tid & 127;
            int y = y0 + half;

            // wait for prep
            if (tid == 0) {
                while (*((volatile int*)&d_prep_ctr) < NPREP) __nanosleep(64);
            }
            __syncthreads();

            if (tid < KBOX) {
                int base = b*KBOX + tid;
                float i2sy = d_i2sy[base];
                int cy = d_cy[base], hr = d_hr[base], act = d_act[base];
                sx1[tid] = d_bx1[base]; sy1s[tid] = d_by1[base];
                sx2[tid] = d_bx2[base]; sy2s[tid] = d_by2[base];
                scoef[tid] = d_coef[base]; si2sx[tid] = d_i2sx[base];
                scx[tid] = d_cx[base]; swr[tid] = d_wr[base]; scls[tid] = d_cls[base];
#pragma unroll
                for (int r = 0; r < 2; r++) {
                    int dy = y0 + r - cy;
                    int rc = act && (abs(dy) <= hr);
                    sgy2[r][tid] = rc ? __expf(-(float)(dy*dy) * i2sy) : 0.0f;
                }
            }
            __syncthreads();
            // warps 0 and 4 build row lists
            if (wrp == 0 || wrp == 4) {
                int row = (wrp == 4);
                int nn = 0;
#pragma unroll
                for (int chunk = 0; chunk < 4; chunk++) {
                    int j = chunk*32 + lane;
                    bool p = sgy2[row][j] > 0.0f;
                    unsigned mb = __ballot_sync(0xffffffffu, p);
                    int pos = nn + __popc(mb & ((1u << lane) - 1u));
                    if (p) slist2[row][pos] = (short)j;
                    nn += __popc(mb);
                }
                if (lane == 0) s_n2[row] = nn;
            }
            __syncthreads();

            int n = s_n2[half];
            const short* mylist = slist2[half];
            const float* mysgy  = sgy2[half];

            // coverage + winner
            unsigned covm[4] = {0u,0u,0u,0u};
            int e_w = -1;
            for (int e = 0; e < n; e++) {
                int j = mylist[e];
                int dx = x - scx[j];
                if (abs(dx) <= swr[j]) {
                    covm[e >> 5] |= 1u << (e & 31);
                    e_w = e;
                }
            }

            const float* hmr = hm + (((size_t)b*NUMC)*OH + y)*OW + x;

            for (int e = 0; e < n; e++) {
                if (!((covm[e >> 5] >> (e & 31)) & 1u)) continue;
                int j = mylist[e];
                int c = scls[j];
                float dxf = (float)(x - scx[j]);
                float g = mysgy[j] * __expf(-dxf*dxf * si2sx[j]);
                bool rep = true;
                for (int e2 = 0; e2 < n; e2++) {
                    if (e2 == e) continue;
                    if (!((covm[e2 >> 5] >> (e2 & 31)) & 1u)) continue;
                    int j2 = mylist[e2];
                    if (scls[j2] != c) continue;
                    float dx2 = (float)(x - scx[j2]);
                    float g2 = mysgy[j2] * __expf(-dx2*dx2 * si2sx[j2]);
                    if (g2 > g || (g2 == g && e2 < e)) { rep = false; break; }
                }
                if (!rep) continue;
                float xv = hmr[(size_t)c * PLANE];
                float p;
                float u = focal_neg_base(xv, p);
                if (g == 1.0f) {
                    float omp = 1.0f - p;
                    float vv = __logf(p) * omp * omp;
                    lsum += vv - u;
                    lnp++;
                } else {
                    float omh = 1.0f - g;
                    float w4 = omh * omh; w4 *= w4;
                    lsum += u * (w4 - 1.0f);
                }
            }

            if (e_w >= 0) {
                int j = mylist[e_w];
                float dxf = (float)(x - scx[j]);
                float g = mysgy[j] * __expf(-dxf*dxf * si2sx[j]);
                float rw = g * scoef[j];
                size_t pbase = (((size_t)b*4)*OH + y)*OW + x;
                float pl = wh[pbase            ] * 16.0f;
                float pt = wh[pbase +   PLANE  ] * 16.0f;
                float pr = wh[pbase + 2*PLANE  ] * 16.0f;
                float pb = wh[pbase + 3*PLANE  ] * 16.0f;
                float xs = (float)x * 4.0f, ys = (float)y * 4.0f;
                float tl = xs - sx1[j];
                float tt = ys - sy1s[j];
                float tr = sx2[j] - xs;
                float tb = sy2s[j] - ys;
                float ta = (tl + tr) * (tt + tb);
                float pa = (pl + pr) * (pt + pb);
                float wi = fminf(pl, tl) + fminf(pr, tr);
                float hi = fminf(pt, tt) + fminf(pb, tb);
                float ai = wi * hi;
                float au = ta + pa - ai;
                float iou = (ai + 1.0f) / (au + 1.0f);
                lwhn = (rw > 0.0f) ? (1.0f - iou) * rw : 0.0f;
                lrw = rw;
            }
        }
    }

    // ================= block reduce -> partial slot =================
    for (int off = 16; off; off >>= 1) {
        lsum += __shfl_down_sync(0xffffffffu, lsum, off);
        lwhn += __shfl_down_sync(0xffffffffu, lwhn, off);
        lrw  += __shfl_down_sync(0xffffffffu, lrw,  off);
        lnp  += __shfl_down_sync(0xffffffffu, lnp,  off);
    }
    __shared__ float r0[8], r1[8], r2[8];
    __shared__ int   r3[8];
    if (lane == 0) { r0[wrp]=lsum; r1[wrp]=lwhn; r2[wrp]=lrw; r3[wrp]=lnp; }
    __syncthreads();
    if (tid == 0) {
        float a=0.f, c1=0.f, c2=0.f; int np=0;
#pragma unroll
        for (int i = 0; i < 8; i++) { a+=r0[i]; c1+=r1[i]; c2+=r2[i]; np+=r3[i]; }
        d_part_hm[bid]  = a;
        d_part_whn[bid] = c1;
        d_part_rw[bid]  = c2;
        d_part_np[bid]  = np;
    }

    // ================= last-block final reduce =================
    __shared__ bool amLast;
    __threadfence();
    __syncthreads();
    if (tid == 0)
        amLast = (atomicAdd(&d_done_ctr, 1u) == (unsigned)(NBLK - 1));
    __syncthreads();
    if (amLast) {
        double shm = 0.0, swn = 0.0, srw = 0.0;
        int snp = 0;
        for (int i = tid; i < NBLK; i += 256) {
            shm += (double)d_part_hm[i];
            swn += (double)d_part_whn[i];
            srw += (double)d_part_rw[i];
            snp += d_part_np[i];
        }
        // warp reduce (doubles via two 32-bit shuffles through __shfl_down_sync on double is supported)
        for (int off = 16; off; off >>= 1) {
            shm += __shfl_down_sync(0xffffffffu, shm, off);
            swn += __shfl_down_sync(0xffffffffu, swn, off);
            srw += __shfl_down_sync(0xffffffffu, srw, off);
            snp += __shfl_down_sync(0xffffffffu, snp, off);
        }
        __shared__ double q0[8], q1[8], q2[8];
        __shared__ int    q3[8];
        if (lane == 0) { q0[wrp]=shm; q1[wrp]=swn; q2[wrp]=srw; q3[wrp]=snp; }
        __syncthreads();
        if (tid == 0) {
            double thm=0.0, twn=0.0, trw=0.0; int tnp=0;
#pragma unroll
            for (int i = 0; i < 8; i++) { thm+=q0[i]; twn+=q1[i]; trw+=q2[i]; tnp+=q3[i]; }
            double hml = (tnp > 0) ? (-thm / (double)(tnp < 1 ? 1 : tnp)) : -thm;
            double whl = twn / fmax(trw, 1.0);
            out[0] = (float)(hml + whl);
            d_done_ctr = 0u;       // self-reset for next replay
            d_prep_ctr = 0;
        }
    }
}

extern "C" void kernel_launch(void* const* d_in, const int* in_sizes, int n_in,
                              void* d_out, int out_size) {
    const float* hm   = (const float*)d_in[0];
    const float* wh   = (const float*)d_in[1];
    const float* tgt  = (const float*)d_in[2];
    const void*  mask = (const void*)d_in[3];
    float* out = (float*)d_out;
    (void)in_sizes; (void)n_in; (void)out_size;

    mega_kernel<<<NBLK, 256>>>(hm, wh, tgt, mask, out);
}